// round 12
// baseline (speedup 1.0000x reference)
#include <cuda_runtime.h>
#include <cuda_bf16.h>
#include <cstdint>
#include <math.h>

#define C256 256

// ---------------------------------------------------------------------------
// Scratch (device globals; no allocations allowed)
// ---------------------------------------------------------------------------
__device__ __nv_bfloat16 g_Wh[4][C256 * C256];
__device__ __nv_bfloat16 g_P0[8 * 6400 * C256];
__device__ __nv_bfloat16 g_P1[8 * 1600 * C256];
__device__ __nv_bfloat16 g_P2[8 *  400 * C256];
__device__ __nv_bfloat16 g_P3[8 *  100 * C256];
__device__ float g_partials[8 * 50 * 6];
__device__ unsigned int g_ticket;   // zero-init; last pair_sums block resets it

__device__ __forceinline__ uint32_t smem_to_u32(const void* p) {
    uint32_t a;
    asm("{ .reg .u64 t; cvta.to.shared.u64 t, %1; cvt.u32.u64 %0, t; }"
        : "=r"(a) : "l"(p));
    return a;
}

#define CP16(dst, src, sz) \
    asm volatile("cp.async.cg.shared.global [%0], [%1], 16, %2;" \
                 :: "r"(dst), "l"(src), "r"(sz))
#define CP_COMMIT() asm volatile("cp.async.commit_group;" ::: "memory")
#define CP_WAIT0()  asm volatile("cp.async.wait_group 0;" ::: "memory")

__device__ __forceinline__ void ldx4(uint32_t* r, uint32_t addr) {
    asm volatile("ldmatrix.sync.aligned.m8n8.x4.shared.b16 {%0,%1,%2,%3}, [%4];"
                 : "=r"(r[0]), "=r"(r[1]), "=r"(r[2]), "=r"(r[3]) : "r"(addr));
}
__device__ __forceinline__ void ldx4t(uint32_t* r, uint32_t addr) {
    asm volatile("ldmatrix.sync.aligned.m8n8.x4.trans.shared.b16 {%0,%1,%2,%3}, [%4];"
                 : "=r"(r[0]), "=r"(r[1]), "=r"(r[2]), "=r"(r[3]) : "r"(addr));
}
__device__ __forceinline__ void mma16816(float* d, const uint32_t* a, const uint32_t* b) {
    asm volatile("mma.sync.aligned.m16n8k16.row.col.f32.bf16.bf16.f32 "
                 "{%0,%1,%2,%3}, {%4,%5,%6,%7}, {%8,%9}, {%0,%1,%2,%3};"
                 : "+f"(d[0]), "+f"(d[1]), "+f"(d[2]), "+f"(d[3])
                 : "r"(a[0]), "r"(a[1]), "r"(a[2]), "r"(a[3]), "r"(b[0]), "r"(b[1]));
}

// ---------------------------------------------------------------------------
// Kernel 0: W -> bf16 (float4 vectorized)
// ---------------------------------------------------------------------------
__global__ void prep_w(const float* __restrict__ w0, const float* __restrict__ w1,
                       const float* __restrict__ w2, const float* __restrict__ w3)
{
    const int s = blockIdx.y;
    const float* w = (s == 0) ? w0 : (s == 1) ? w1 : (s == 2) ? w2 : w3;
    const int idx = blockIdx.x * 256 + threadIdx.x;       // grid.x=64 -> 16384 float4
    const float4 v = ((const float4*)w)[idx];
    __nv_bfloat162 lo = __float22bfloat162_rn(make_float2(v.x, v.y));
    __nv_bfloat162 hi = __float22bfloat162_rn(make_float2(v.z, v.w));
    uint2 pk;
    pk.x = *(uint32_t*)&lo;
    pk.y = *(uint32_t*)&hi;
    ((uint2*)g_Wh[s])[idx] = pk;
}

// ---------------------------------------------------------------------------
// Kernel 1: fused HMMA bf16 GEMM, BM=256, BN=128, BK=64 (4 k-chunks).
// 512 threads (4x4 warps, warp tile 64x32), 2-stage cp.async.
// ---------------------------------------------------------------------------
#define A_ROWB 144u                     // 64 bf16 (128B) + 16B pad
#define A_TILE (256u * A_ROWB)          // 36864
#define B_ROWB 272u                     // 128 bf16 + 8 pad
#define B_TILE (64u * B_ROWB)           // 17408
#define STAGE  (A_TILE + B_TILE)        // 54272
#define EP_ROWB 528u                    // 264 bf16 (256 + 8 pad)
#define GEMM_SMEM (2u * STAGE)          // 108544 (> 128*EP_ROWB = 67584)

__global__ __launch_bounds__(512, 1)
void gemm_fused(const float* __restrict__ f0, const float* __restrict__ f1,
                const float* __restrict__ f2, const float* __restrict__ f3,
                const float* __restrict__ b0, const float* __restrict__ b1,
                const float* __restrict__ b2, const float* __restrict__ b3)
{
    extern __shared__ char sm[];
    const uint32_t sb = smem_to_u32(sm);
    const int tid = threadIdx.x;
    const int wid = tid >> 5, lane = tid & 31;

    // ---- scale lookup (blocks: 400 | 104 | 32 | 8) ----
    const int id = blockIdx.x;
    int s, off, L;
    const float* F;
    const float* bias;
    __nv_bfloat16* P;
    if (id < 400)      { s = 0; off = 0;   L = 6400; F = f0; bias = b0; P = g_P0; }
    else if (id < 504) { s = 1; off = 400; L = 1600; F = f1; bias = b1; P = g_P1; }
    else if (id < 536) { s = 2; off = 504; L = 400;  F = f2; bias = b2; P = g_P2; }
    else               { s = 3; off = 536; L = 100;  F = f3; bias = b3; P = g_P3; }
    const int local = id - off;
    const int l0    = (local >> 3) * 128;
    const int batch = local & 7;

    const __nv_bfloat16* Wh = g_Wh[s];
    const float* Fb = F + (size_t)batch * C256 * L;
    __nv_bfloat16* Pb = P + (size_t)batch * L * C256;

    // ---- A cp.async slots: row = tid>>1 (0..255), 64B half = tid&1 ----
    const int arow = tid >> 1;
    const int ah   = (tid & 1) * 64;   // byte offset within the 128B chunk-row
    const uint32_t aOff = arow * A_ROWB + ah;
    const char* srcAh = (const char*)(Wh + (size_t)arow * C256) + ah;

#define ISSUE_A(kc, st) do {                                                  \
        const uint32_t base = sb + (uint32_t)(st) * STAGE;                    \
        const int ko = (kc) * 128;                                            \
        CP16(base + aOff,      srcAh + ko,      16u);                         \
        CP16(base + aOff + 16, srcAh + ko + 16, 16u);                         \
        CP16(base + aOff + 32, srcAh + ko + 32, 16u);                         \
        CP16(base + aOff + 48, srcAh + ko + 48, 16u);                         \
        CP_COMMIT();                                                          \
    } while (0)

    // ---- B load slots: channel = tid>>3 (0..63), 16 locations at (tid&7)*16 ----
    const int cloc = tid >> 3;
    const int lcol = (tid & 7) * 16;
    float4 v[4];

#define LDG_B(kc) do {                                                        \
        const int ch = (kc) * 64 + cloc;                                      \
        const float* rp = Fb + (size_t)ch * L + l0 + lcol;                    \
        _Pragma("unroll")                                                     \
        for (int i = 0; i < 4; ++i)                                           \
            v[i] = (l0 + lcol + i * 4 < L) ? *(const float4*)(rp + i * 4)     \
                                           : make_float4(0.f, 0.f, 0.f, 0.f); \
    } while (0)

#define STS_B(st) do {                                                        \
        char* bp = sm + (size_t)(st) * STAGE + A_TILE                         \
                   + (size_t)cloc * B_ROWB + lcol * 2;                        \
        uint4 p0, p1;                                                         \
        __nv_bfloat162 t;                                                     \
        t = __float22bfloat162_rn(make_float2(v[0].x, v[0].y)); p0.x = *(uint32_t*)&t; \
        t = __float22bfloat162_rn(make_float2(v[0].z, v[0].w)); p0.y = *(uint32_t*)&t; \
        t = __float22bfloat162_rn(make_float2(v[1].x, v[1].y)); p0.z = *(uint32_t*)&t; \
        t = __float22bfloat162_rn(make_float2(v[1].z, v[1].w)); p0.w = *(uint32_t*)&t; \
        t = __float22bfloat162_rn(make_float2(v[2].x, v[2].y)); p1.x = *(uint32_t*)&t; \
        t = __float22bfloat162_rn(make_float2(v[2].z, v[2].w)); p1.y = *(uint32_t*)&t; \
        t = __float22bfloat162_rn(make_float2(v[3].x, v[3].y)); p1.z = *(uint32_t*)&t; \
        t = __float22bfloat162_rn(make_float2(v[3].z, v[3].w)); p1.w = *(uint32_t*)&t; \
        *(uint4*)(bp)      = p0;                                              \
        *(uint4*)(bp + 16) = p1;                                              \
    } while (0)

    float acc[4][4][4];
#pragma unroll
    for (int i = 0; i < 4; ++i)
#pragma unroll
        for (int j = 0; j < 4; ++j)
#pragma unroll
            for (int k = 0; k < 4; ++k) acc[i][j][k] = 0.f;

    const int r8 = lane & 7, sel = lane >> 3;
    const int warp_m = wid >> 2, warp_n = wid & 3;   // 4x4 warp grid
    // A fragment base: row pair select in (sel&1), k-16B select in (sel>>1)
    const uint32_t aRel = (uint32_t)((warp_m * 64 + r8 + (sel & 1) * 8) * A_ROWB
                                     + (sel >> 1) * 16);
    // B [k=64][n=128] trans fragments
    const uint32_t bRel = (uint32_t)(A_TILE
                          + ((sel & 1) * 8 + r8) * B_ROWB
                          + (warp_n * 32 + (sel >> 1) * 8) * 2);

    LDG_B(0);
    STS_B(0);
    ISSUE_A(0, 0);
    CP_WAIT0();
    __syncthreads();

    for (int kc = 0; kc < 4; ++kc) {
        const int st = kc & 1;
        if (kc < 3) {
            LDG_B(kc + 1);
            ISSUE_A(kc + 1, st ^ 1);
        }

        const uint32_t stage = sb + (uint32_t)st * STAGE;
#pragma unroll
        for (int ks = 0; ks < 4; ++ks) {     // four k16 steps per chunk
            uint32_t bf[8];
            ldx4t(bf,     stage + bRel + ks * 16 * B_ROWB);
            ldx4t(bf + 4, stage + bRel + ks * 16 * B_ROWB + 32);
            uint32_t af[4];
#pragma unroll
            for (int mt = 0; mt < 4; ++mt) {
                ldx4(af, stage + aRel + ks * 32 + mt * 16 * A_ROWB);
#pragma unroll
                for (int nt = 0; nt < 4; ++nt)
                    mma16816(acc[mt][nt], af, bf + (nt >> 1) * 4 + (nt & 1) * 2);
            }
        }

        if (kc < 3) {
            STS_B(st ^ 1);
            CP_WAIT0();
        }
        __syncthreads();
    }

    // ---- epilogue: bias add, stage [n][m] bf16 (528B rows), 512B stores ----
    {
        float bv[4][2];
#pragma unroll
        for (int mt = 0; mt < 4; ++mt) {
            const int m = warp_m * 64 + mt * 16 + (lane >> 2);
            bv[mt][0] = bias[m];
            bv[mt][1] = bias[m + 8];
        }
        __nv_bfloat16* ep = (__nv_bfloat16*)sm;
#pragma unroll
        for (int mt = 0; mt < 4; ++mt) {
            const int m = warp_m * 64 + mt * 16 + (lane >> 2);
#pragma unroll
            for (int nt = 0; nt < 4; ++nt) {
                const int n = warp_n * 32 + nt * 8 + (lane & 3) * 2;
                ep[(size_t)n       * 264 + m]     = __float2bfloat16(acc[mt][nt][0] + bv[mt][0]);
                ep[(size_t)(n + 1) * 264 + m]     = __float2bfloat16(acc[mt][nt][1] + bv[mt][0]);
                ep[(size_t)n       * 264 + m + 8] = __float2bfloat16(acc[mt][nt][2] + bv[mt][1]);
                ep[(size_t)(n + 1) * 264 + m + 8] = __float2bfloat16(acc[mt][nt][3] + bv[mt][1]);
            }
        }
        __syncthreads();
        const int n = tid >> 2, quarter = tid & 3;
        if (l0 + n < L) {
            const uint4* src = (const uint4*)((const char*)sm + (size_t)n * EP_ROWB + quarter * 128);
            uint4* dst = (uint4*)(Pb + (size_t)(l0 + n) * C256 + quarter * 64);
#pragma unroll
            for (int i = 0; i < 8; ++i) dst[i] = src[i];
        }
    }
#undef ISSUE_A
#undef LDG_B
#undef STS_B
}

// ---------------------------------------------------------------------------
// Phase 2: cosine pair sums, one 2x2 full-res block per 8-lane group.
// ---------------------------------------------------------------------------
__device__ __forceinline__ void exp8(uint4 u, float* f) {
    f[0] = __uint_as_float(u.x << 16); f[1] = __uint_as_float(u.x & 0xffff0000u);
    f[2] = __uint_as_float(u.y << 16); f[3] = __uint_as_float(u.y & 0xffff0000u);
    f[4] = __uint_as_float(u.z << 16); f[5] = __uint_as_float(u.z & 0xffff0000u);
    f[6] = __uint_as_float(u.w << 16); f[7] = __uint_as_float(u.w & 0xffff0000u);
}

__global__ __launch_bounds__(256)
void pair_sums(float* __restrict__ out)
{
    const int b    = blockIdx.y;
    const int blk  = blockIdx.x;          // 0..49
    const int warp = threadIdx.x >> 5;    // 0..7
    const int lane = threadIdx.x & 31;
    const int g    = lane >> 3;           // group 0..3
    const int q    = lane & 7;            // lane in group

    const int G  = blk * 32 + warp * 4 + g;   // 2x2 block id, 0..1599
    const int bh = G / 40;
    const int bw = G - bh * 40;
    const int l00 = (2 * bh) * 80 + 2 * bw;

    const uint4* x0a = (const uint4*)(g_P0 + (size_t)(b * 6400 + l00)      * C256);
    const uint4* x0b = (const uint4*)(g_P0 + (size_t)(b * 6400 + l00 + 1)  * C256);
    const uint4* x0c = (const uint4*)(g_P0 + (size_t)(b * 6400 + l00 + 80) * C256);
    const uint4* x0d = (const uint4*)(g_P0 + (size_t)(b * 6400 + l00 + 81) * C256);
    const uint4* x1  = (const uint4*)(g_P1 + (size_t)(b * 1600 + bh * 40 + bw) * C256);
    const uint4* x2  = (const uint4*)(g_P2 + (size_t)(b *  400 + (bh >> 1) * 20 + (bw >> 1)) * C256);
    const uint4* x3  = (const uint4*)(g_P3 + (size_t)(b *  100 + (bh >> 2) * 10 + (bw >> 2)) * C256);

    float d[22];
#pragma unroll
    for (int k = 0; k < 22; ++k) d[k] = 0.f;

#pragma unroll
    for (int j = 0; j < 4; ++j) {
        const int idx = q + 8 * j;
        float fa[8], fb[8], fc[8], fd[8], f1[8], f2[8], f3[8];
        exp8(x0a[idx], fa);
        exp8(x0b[idx], fb);
        exp8(x0c[idx], fc);
        exp8(x0d[idx], fd);
        exp8(x1[idx],  f1);
        exp8(x2[idx],  f2);
        exp8(x3[idx],  f3);
#pragma unroll
        for (int e = 0; e < 8; ++e) {
            d[0]  += fa[e] * fa[e];
            d[1]  += fb[e] * fb[e];
            d[2]  += fc[e] * fc[e];
            d[3]  += fd[e] * fd[e];
            d[4]  += fa[e] * f1[e];
            d[5]  += fb[e] * f1[e];
            d[6]  += fc[e] * f1[e];
            d[7]  += fd[e] * f1[e];
            d[8]  += fa[e] * f2[e];
            d[9]  += fb[e] * f2[e];
            d[10] += fc[e] * f2[e];
            d[11] += fd[e] * f2[e];
            d[12] += fa[e] * f3[e];
            d[13] += fb[e] * f3[e];
            d[14] += fc[e] * f3[e];
            d[15] += fd[e] * f3[e];
            d[16] += f1[e] * f1[e];
            d[17] += f2[e] * f2[e];
            d[18] += f3[e] * f3[e];
            d[19] += f1[e] * f2[e];
            d[20] += f1[e] * f3[e];
            d[21] += f2[e] * f3[e];
        }
    }

#pragma unroll
    for (int off = 4; off > 0; off >>= 1) {
#pragma unroll
        for (int k = 0; k < 22; ++k)
            d[k] += __shfl_xor_sync(0xFFFFFFFFu, d[k], off);
    }

    __shared__ float sh[32][6];
    __shared__ unsigned int sh_last;
    if (q == 0) {
        const float n1 = sqrtf(d[16]);
        const float n2 = sqrtf(d[17]);
        const float n3 = sqrtf(d[18]);
        float a01 = 0.f, a02 = 0.f, a03 = 0.f;
#pragma unroll
        for (int p = 0; p < 4; ++p) {
            const float n0 = sqrtf(d[p]);
            a01 += d[4 + p]  / fmaxf(n0 * n1, 1e-8f);
            a02 += d[8 + p]  / fmaxf(n0 * n2, 1e-8f);
            a03 += d[12 + p] / fmaxf(n0 * n3, 1e-8f);
        }
        const int gi = warp * 4 + g;
        sh[gi][0] = a01;
        sh[gi][1] = a02;
        sh[gi][2] = a03;
        sh[gi][3] = 4.f * (d[19] / fmaxf(n1 * n2, 1e-8f));
        sh[gi][4] = 4.f * (d[20] / fmaxf(n1 * n3, 1e-8f));
        sh[gi][5] = 4.f * (d[21] / fmaxf(n2 * n3, 1e-8f));
    }
    __syncthreads();

    if (threadIdx.x == 0) {
        float* dst = &g_partials[((size_t)b * 50 + blk) * 6];
#pragma unroll
        for (int k = 0; k < 6; ++k) {
            float ss = 0.f;
#pragma unroll
            for (int i = 0; i < 32; ++i) ss += sh[i][k];
            dst[k] = ss;
        }
        __threadfence();
        sh_last = (atomicAdd(&g_ticket, 1u) == 399u);
    }
    __syncthreads();

    if (sh_last) {
        __threadfence();
        const int t = threadIdx.x;
        __shared__ float red[8][6];
        if (t < 48) {
            const int bb = t / 6, k = t % 6;
            float ss = 0.f;
            for (int i = 0; i < 50; ++i)
                ss += g_partials[((size_t)bb * 50 + i) * 6 + k];
            red[bb][k] = ss;
        }
        __syncthreads();
        if (t < 8) {
            const float inv = 1.0f / 6400.0f;
            float a[4][4];
            a[0][0] = a[1][1] = a[2][2] = a[3][3] = 1.0f;
            a[0][1] = a[1][0] = red[t][0] * inv;
            a[0][2] = a[2][0] = red[t][1] * inv;
            a[0][3] = a[3][0] = red[t][2] * inv;
            a[1][2] = a[2][1] = red[t][3] * inv;
            a[1][3] = a[3][1] = red[t][4] * inv;
            a[2][3] = a[3][2] = red[t][5] * inv;
            for (int i = 0; i < 4; ++i) {
                float m = a[i][0];
                for (int j = 1; j < 4; ++j) m = fmaxf(m, a[i][j]);
                float e[4], sum = 0.f;
                for (int j = 0; j < 4; ++j) { e[j] = expf(a[i][j] - m); sum += e[j]; }
                for (int j = 0; j < 4; ++j) out[t * 16 + i * 4 + j] = e[j] / sum;
            }
        }
        if (t == 0) g_ticket = 0;
    }
}

// ---------------------------------------------------------------------------
extern "C" void kernel_launch(void* const* d_in, const int* in_sizes, int n_in,
                              void* d_out, int out_size)
{
    const float* f[4]  = {nullptr, nullptr, nullptr, nullptr};
    const float* w[4]  = {nullptr, nullptr, nullptr, nullptr};
    const float* bs[4] = {nullptr, nullptr, nullptr, nullptr};
    int wi = 0, bi = 0;
    for (int i = 0; i < n_in; ++i) {
        long sz = in_sizes[i];
        const float* p = (const float*)d_in[i];
        if      (sz == 65536)    { if (wi < 4) w[wi++]  = p; }
        else if (sz == 256)      { if (bi < 4) bs[bi++] = p; }
        else if (sz == 13107200) f[0] = p;   // 8*256*6400
        else if (sz == 3276800)  f[1] = p;   // 8*256*1600
        else if (sz == 819200)   f[2] = p;   // 8*256*400
        else if (sz == 204800)   f[3] = p;   // 8*256*100
    }

    prep_w<<<dim3(64, 4), 256>>>(w[0], w[1], w[2], w[3]);

    cudaFuncSetAttribute(gemm_fused, cudaFuncAttributeMaxDynamicSharedMemorySize, GEMM_SMEM);
    gemm_fused<<<544, 512, GEMM_SMEM>>>(f[0], f[1], f[2], f[3],
                                        bs[0], bs[1], bs[2], bs[3]);

    pair_sums<<<dim3(50, 8), 256>>>((float*)d_out);
}

// round 13
// speedup vs baseline: 1.0889x; 1.0889x over previous
#include <cuda_runtime.h>
#include <cuda_bf16.h>
#include <cstdint>
#include <math.h>

#define C256 256

// ---------------------------------------------------------------------------
// Scratch (device globals; no allocations allowed)
// ---------------------------------------------------------------------------
__device__ __nv_bfloat16 g_Wh[4][C256 * C256];
__device__ __nv_bfloat16 g_P1[8 * 1600 * C256];
__device__ __nv_bfloat16 g_P2[8 *  400 * C256];
__device__ __nv_bfloat16 g_P3[8 *  100 * C256];
__device__ float g_part_fine[8 * 50 * 3];
__device__ float g_part_coarse[8 * 5 * 3];
__device__ unsigned int g_ticket;   // zero-init; last gemm0 block resets it

__device__ __forceinline__ uint32_t smem_to_u32(const void* p) {
    uint32_t a;
    asm("{ .reg .u64 t; cvta.to.shared.u64 t, %1; cvt.u32.u64 %0, t; }"
        : "=r"(a) : "l"(p));
    return a;
}

#define CP16(dst, src, sz) \
    asm volatile("cp.async.cg.shared.global [%0], [%1], 16, %2;" \
                 :: "r"(dst), "l"(src), "r"(sz))
#define CP_COMMIT() asm volatile("cp.async.commit_group;" ::: "memory")
#define CP_WAIT0()  asm volatile("cp.async.wait_group 0;" ::: "memory")

__device__ __forceinline__ void ldx4(uint32_t* r, uint32_t addr) {
    asm volatile("ldmatrix.sync.aligned.m8n8.x4.shared.b16 {%0,%1,%2,%3}, [%4];"
                 : "=r"(r[0]), "=r"(r[1]), "=r"(r[2]), "=r"(r[3]) : "r"(addr));
}
__device__ __forceinline__ void ldx4t(uint32_t* r, uint32_t addr) {
    asm volatile("ldmatrix.sync.aligned.m8n8.x4.trans.shared.b16 {%0,%1,%2,%3}, [%4];"
                 : "=r"(r[0]), "=r"(r[1]), "=r"(r[2]), "=r"(r[3]) : "r"(addr));
}
__device__ __forceinline__ void mma16816(float* d, const uint32_t* a, const uint32_t* b) {
    asm volatile("mma.sync.aligned.m16n8k16.row.col.f32.bf16.bf16.f32 "
                 "{%0,%1,%2,%3}, {%4,%5,%6,%7}, {%8,%9}, {%0,%1,%2,%3};"
                 : "+f"(d[0]), "+f"(d[1]), "+f"(d[2]), "+f"(d[3])
                 : "r"(a[0]), "r"(a[1]), "r"(a[2]), "r"(a[3]), "r"(b[0]), "r"(b[1]));
}
__device__ __forceinline__ void exp8(uint4 u, float* f) {
    f[0] = __uint_as_float(u.x << 16); f[1] = __uint_as_float(u.x & 0xffff0000u);
    f[2] = __uint_as_float(u.y << 16); f[3] = __uint_as_float(u.y & 0xffff0000u);
    f[4] = __uint_as_float(u.z << 16); f[5] = __uint_as_float(u.z & 0xffff0000u);
    f[6] = __uint_as_float(u.w << 16); f[7] = __uint_as_float(u.w & 0xffff0000u);
}

// ---------------------------------------------------------------------------
// Kernel 0: W -> bf16 (float4 vectorized)
// ---------------------------------------------------------------------------
__global__ void prep_w(const float* __restrict__ w0, const float* __restrict__ w1,
                       const float* __restrict__ w2, const float* __restrict__ w3)
{
    const int s = blockIdx.y;
    const float* w = (s == 0) ? w0 : (s == 1) ? w1 : (s == 2) ? w2 : w3;
    const int idx = blockIdx.x * 256 + threadIdx.x;
    const float4 v = ((const float4*)w)[idx];
    __nv_bfloat162 lo = __float22bfloat162_rn(make_float2(v.x, v.y));
    __nv_bfloat162 hi = __float22bfloat162_rn(make_float2(v.z, v.w));
    uint2 pk;
    pk.x = *(uint32_t*)&lo;
    pk.y = *(uint32_t*)&hi;
    ((uint2*)g_Wh[s])[idx] = pk;
}

// ---------------------------------------------------------------------------
// Shared GEMM tile config: BM=256, BN=128, BK=32, 512 threads (4x4 warps).
// ---------------------------------------------------------------------------
#define A_ROWB 80u
#define A_TILE (256u * A_ROWB)          // 20480
#define B_ROWB 272u
#define B_TILE (32u * B_ROWB)           // 8704
#define STAGE  (A_TILE + B_TILE)        // 29184
#define EP_ROWB 528u
#define GEMM_SMEM (128u * EP_ROWB)      // 67584 > 2*STAGE

// common mainloop macros -----------------------------------------------------
#define GEMM_DECLS()                                                           \
    const uint32_t sb = smem_to_u32(sm);                                       \
    const int tid = threadIdx.x;                                               \
    const int wid = tid >> 5, lane = tid & 31;                                 \
    const int arow = tid >> 1;                                                 \
    const int c2   = (tid & 1) * 2;                                            \
    const uint32_t aOff = arow * A_ROWB + c2 * 16;                             \
    const int cloc = tid >> 4;                                                 \
    const int lcol = (tid & 15) * 8;                                           \
    const int r8 = lane & 7, sel = lane >> 3;                                  \
    const int warp_m = wid >> 2, warp_n = wid & 3;                             \
    const uint32_t aRel = (uint32_t)((warp_m * 64 + r8 + (sel & 1) * 8) * A_ROWB \
                                     + (sel >> 1) * 16);                       \
    const uint32_t bRel = (uint32_t)(A_TILE                                    \
                          + ((sel & 1) * 8 + r8) * B_ROWB                      \
                          + (warp_n * 32 + (sel >> 1) * 8) * 2)

#define ISSUE_A(kc, st) do {                                                  \
        const uint32_t base = sb + (uint32_t)(st) * STAGE;                    \
        const int ko = (kc) * 64;                                             \
        CP16(base + aOff,      srcAh + ko,      16u);                         \
        CP16(base + aOff + 16, srcAh + ko + 16, 16u);                         \
        CP_COMMIT();                                                          \
    } while (0)

#define STS_B(st) do {                                                        \
        char* bp = sm + (size_t)(st) * STAGE + A_TILE                         \
                   + (size_t)cloc * B_ROWB + lcol * 2;                        \
        uint4 p0;                                                             \
        __nv_bfloat162 t;                                                     \
        t = __float22bfloat162_rn(make_float2(v[0].x, v[0].y)); p0.x = *(uint32_t*)&t; \
        t = __float22bfloat162_rn(make_float2(v[0].z, v[0].w)); p0.y = *(uint32_t*)&t; \
        t = __float22bfloat162_rn(make_float2(v[1].x, v[1].y)); p0.z = *(uint32_t*)&t; \
        t = __float22bfloat162_rn(make_float2(v[1].z, v[1].w)); p0.w = *(uint32_t*)&t; \
        *(uint4*)(bp) = p0;                                                   \
    } while (0)

#define GEMM_MAINLOOP(LDG_B_MACRO)                                            \
    float acc[4][4][4];                                                       \
    _Pragma("unroll")                                                         \
    for (int i = 0; i < 4; ++i)                                               \
        _Pragma("unroll")                                                     \
        for (int j = 0; j < 4; ++j)                                           \
            _Pragma("unroll")                                                 \
            for (int k = 0; k < 4; ++k) acc[i][j][k] = 0.f;                   \
    LDG_B_MACRO(0);                                                           \
    STS_B(0);                                                                 \
    ISSUE_A(0, 0);                                                            \
    CP_WAIT0();                                                               \
    __syncthreads();                                                          \
    for (int kc = 0; kc < 8; ++kc) {                                          \
        const int st = kc & 1;                                                \
        if (kc < 7) { LDG_B_MACRO(kc + 1); ISSUE_A(kc + 1, st ^ 1); }         \
        const uint32_t stage = sb + (uint32_t)st * STAGE;                     \
        _Pragma("unroll")                                                     \
        for (int ks = 0; ks < 2; ++ks) {                                      \
            uint32_t bf[8];                                                   \
            ldx4t(bf,     stage + bRel + ks * 16 * B_ROWB);                   \
            ldx4t(bf + 4, stage + bRel + ks * 16 * B_ROWB + 32);              \
            uint32_t af[4];                                                   \
            _Pragma("unroll")                                                 \
            for (int mt = 0; mt < 4; ++mt) {                                  \
                ldx4(af, stage + aRel + ks * 32 + mt * 16 * A_ROWB);          \
                _Pragma("unroll")                                             \
                for (int nt = 0; nt < 4; ++nt)                                \
                    mma16816(acc[mt][nt], af, bf + (nt >> 1) * 4 + (nt & 1) * 2); \
            }                                                                 \
        }                                                                     \
        if (kc < 7) { STS_B(st ^ 1); CP_WAIT0(); }                            \
        __syncthreads();                                                      \
    }

#define GEMM_STAGE_EP()                                                       \
    {                                                                         \
        float bv[4][2];                                                       \
        _Pragma("unroll")                                                     \
        for (int mt = 0; mt < 4; ++mt) {                                      \
            const int m = warp_m * 64 + mt * 16 + (lane >> 2);                \
            bv[mt][0] = bias[m];                                              \
            bv[mt][1] = bias[m + 8];                                          \
        }                                                                     \
        __nv_bfloat16* ep = (__nv_bfloat16*)sm;                               \
        _Pragma("unroll")                                                     \
        for (int mt = 0; mt < 4; ++mt) {                                      \
            const int m = warp_m * 64 + mt * 16 + (lane >> 2);                \
            _Pragma("unroll")                                                 \
            for (int nt = 0; nt < 4; ++nt) {                                  \
                const int n = warp_n * 32 + nt * 8 + (lane & 3) * 2;          \
                ep[(size_t)n       * 264 + m]     = __float2bfloat16(acc[mt][nt][0] + bv[mt][0]); \
                ep[(size_t)(n + 1) * 264 + m]     = __float2bfloat16(acc[mt][nt][1] + bv[mt][0]); \
                ep[(size_t)n       * 264 + m + 8] = __float2bfloat16(acc[mt][nt][2] + bv[mt][1]); \
                ep[(size_t)(n + 1) * 264 + m + 8] = __float2bfloat16(acc[mt][nt][3] + bv[mt][1]); \
            }                                                                 \
        }                                                                     \
        __syncthreads();                                                      \
    }

// ---------------------------------------------------------------------------
// Kernel 1: gemm for scales 1..3, writes P1..P3.
// ---------------------------------------------------------------------------
__global__ __launch_bounds__(512, 1)
void gemm_small(const float* __restrict__ f1, const float* __restrict__ f2,
                const float* __restrict__ f3, const float* __restrict__ b1,
                const float* __restrict__ b2, const float* __restrict__ b3)
{
    extern __shared__ char sm[];
    GEMM_DECLS();

    const int id = blockIdx.x;
    int s, off, L;
    const float* F;
    const float* bias;
    __nv_bfloat16* P;
    if (id < 104)      { s = 1; off = 0;   L = 1600; F = f1; bias = b1; P = g_P1; }
    else if (id < 136) { s = 2; off = 104; L = 400;  F = f2; bias = b2; P = g_P2; }
    else               { s = 3; off = 136; L = 100;  F = f3; bias = b3; P = g_P3; }
    const int local = id - off;
    const int l0    = (local >> 3) * 128;
    const int batch = local & 7;

    const float* Fb = F + (size_t)batch * C256 * L;
    __nv_bfloat16* Pb = P + (size_t)batch * L * C256;
    const char* srcAh = (const char*)(g_Wh[s] + (size_t)arow * C256) + c2 * 16;

    float4 v[2];
#define LDG_BS(kc) do {                                                       \
        const int ch = (kc) * 32 + cloc;                                      \
        const float* rp = Fb + (size_t)ch * L + l0 + lcol;                    \
        _Pragma("unroll")                                                     \
        for (int i = 0; i < 2; ++i)                                           \
            v[i] = (l0 + lcol + i * 4 < L) ? *(const float4*)(rp + i * 4)     \
                                           : make_float4(0.f, 0.f, 0.f, 0.f); \
    } while (0)

    GEMM_MAINLOOP(LDG_BS);
    GEMM_STAGE_EP();

    const int n = tid >> 2, quarter = tid & 3;
    if (l0 + n < L) {
        const uint4* src = (const uint4*)((const char*)sm + (size_t)n * EP_ROWB + quarter * 128);
        uint4* dst = (uint4*)(Pb + (size_t)(l0 + n) * C256 + quarter * 64);
#pragma unroll
        for (int i = 0; i < 8; ++i) dst[i] = src[i];
    }
#undef LDG_BS
}

// ---------------------------------------------------------------------------
// Kernel 2: scale-0 gemm + fused fine cosine (blocks 0..399),
//           coarse pair sums (blocks 400..439), final softmax (last ticket).
// ---------------------------------------------------------------------------
__global__ __launch_bounds__(512, 1)
void gemm0_fused(const float* __restrict__ f0, const float* __restrict__ b0,
                 float* __restrict__ out)
{
    extern __shared__ char sm[];
    __shared__ float sh2[16][3];
    __shared__ unsigned int sh_last;
    const int id = blockIdx.x;

    if (id < 400) {
        GEMM_DECLS();
        const int l0    = (id >> 3) * 128;
        const int batch = id & 7;
        const float* Fb = f0 + (size_t)batch * C256 * 6400;
        const float* bias = b0;
        const char* srcAh = (const char*)(g_Wh[0] + (size_t)arow * C256) + c2 * 16;

        float4 v[2];
#define LDG_B0(kc) do {                                                       \
        const int ch = (kc) * 32 + cloc;                                      \
        const float* rp = Fb + (size_t)ch * 6400 + l0 + lcol;                 \
        v[0] = *(const float4*)(rp);                                          \
        v[1] = *(const float4*)(rp + 4);                                      \
    } while (0)

        GEMM_MAINLOOP(LDG_B0);
        GEMM_STAGE_EP();

        // ---- fused fine cosine: warp handles 8 pixels, lane = 8 channels ----
        float a01 = 0.f, a02 = 0.f, a03 = 0.f;
        for (int i = 0; i < 8; ++i) {
            const int n = wid * 8 + i;
            const int l = l0 + n;
            const int h = l / 80;
            const int wim = l - h * 80;
            const uint4 u0 = *(const uint4*)(sm + (size_t)n * EP_ROWB + lane * 16);
            const uint4 u1 = ((const uint4*)(g_P1 + (size_t)(batch * 1600 + (h >> 1) * 40 + (wim >> 1)) * C256))[lane];
            const uint4 u2 = ((const uint4*)(g_P2 + (size_t)(batch *  400 + (h >> 2) * 20 + (wim >> 2)) * C256))[lane];
            const uint4 u3 = ((const uint4*)(g_P3 + (size_t)(batch *  100 + (h >> 3) * 10 + (wim >> 3)) * C256))[lane];
            float e0[8], e1[8], e2[8], e3[8];
            exp8(u0, e0); exp8(u1, e1); exp8(u2, e2); exp8(u3, e3);
            float d[7];
#pragma unroll
            for (int k = 0; k < 7; ++k) d[k] = 0.f;
#pragma unroll
            for (int e = 0; e < 8; ++e) {
                d[0] += e0[e] * e0[e];
                d[1] += e1[e] * e1[e];
                d[2] += e2[e] * e2[e];
                d[3] += e3[e] * e3[e];
                d[4] += e0[e] * e1[e];
                d[5] += e0[e] * e2[e];
                d[6] += e0[e] * e3[e];
            }
#pragma unroll
            for (int off = 16; off > 0; off >>= 1) {
#pragma unroll
                for (int k = 0; k < 7; ++k)
                    d[k] += __shfl_xor_sync(0xFFFFFFFFu, d[k], off);
            }
            if (lane == 0) {
                const float n0 = sqrtf(d[0]);
                const float n1 = sqrtf(d[1]);
                const float n2 = sqrtf(d[2]);
                const float n3 = sqrtf(d[3]);
                a01 += d[4] / fmaxf(n0 * n1, 1e-8f);
                a02 += d[5] / fmaxf(n0 * n2, 1e-8f);
                a03 += d[6] / fmaxf(n0 * n3, 1e-8f);
            }
        }
        if (lane == 0) { sh2[wid][0] = a01; sh2[wid][1] = a02; sh2[wid][2] = a03; }
        __syncthreads();
        if (tid == 0) {
            float* dst = &g_part_fine[((size_t)batch * 50 + (id >> 3)) * 3];
#pragma unroll
            for (int k = 0; k < 3; ++k) {
                float ss = 0.f;
#pragma unroll
                for (int i = 0; i < 16; ++i) ss += sh2[i][k];
                dst[k] = ss;
            }
        }
#undef LDG_B0
    } else {
        // ---- coarse pairs over scale-1 grid: block = (batch, 320-loc seg) ----
        const int tid = threadIdx.x;
        const int wid = tid >> 5, lane = tid & 31;
        const int c = id - 400;             // 0..39
        const int batch = c / 5;
        const int seg   = c - batch * 5;    // 0..4
        float a12 = 0.f, a13 = 0.f, a23 = 0.f;
        for (int i = 0; i < 20; ++i) {
            const int loc = seg * 320 + wid * 20 + i;   // 0..1599
            const int h1 = loc / 40;
            const int w1 = loc - h1 * 40;
            const uint4 u1 = ((const uint4*)(g_P1 + (size_t)(batch * 1600 + loc) * C256))[lane];
            const uint4 u2 = ((const uint4*)(g_P2 + (size_t)(batch *  400 + (h1 >> 1) * 20 + (w1 >> 1)) * C256))[lane];
            const uint4 u3 = ((const uint4*)(g_P3 + (size_t)(batch *  100 + (h1 >> 2) * 10 + (w1 >> 2)) * C256))[lane];
            float e1[8], e2[8], e3[8];
            exp8(u1, e1); exp8(u2, e2); exp8(u3, e3);
            float d[6];
#pragma unroll
            for (int k = 0; k < 6; ++k) d[k] = 0.f;
#pragma unroll
            for (int e = 0; e < 8; ++e) {
                d[0] += e1[e] * e1[e];
                d[1] += e2[e] * e2[e];
                d[2] += e3[e] * e3[e];
                d[3] += e1[e] * e2[e];
                d[4] += e1[e] * e3[e];
                d[5] += e2[e] * e3[e];
            }
#pragma unroll
            for (int off = 16; off > 0; off >>= 1) {
#pragma unroll
                for (int k = 0; k < 6; ++k)
                    d[k] += __shfl_xor_sync(0xFFFFFFFFu, d[k], off);
            }
            if (lane == 0) {
                const float n1 = sqrtf(d[0]);
                const float n2 = sqrtf(d[1]);
                const float n3 = sqrtf(d[2]);
                a12 += d[3] / fmaxf(n1 * n2, 1e-8f);
                a13 += d[4] / fmaxf(n1 * n3, 1e-8f);
                a23 += d[5] / fmaxf(n2 * n3, 1e-8f);
            }
        }
        if (lane == 0) { sh2[wid][0] = a12 * 4.f; sh2[wid][1] = a13 * 4.f; sh2[wid][2] = a23 * 4.f; }
        __syncthreads();
        if (tid == 0) {
            float* dst = &g_part_coarse[((size_t)batch * 5 + seg) * 3];
#pragma unroll
            for (int k = 0; k < 3; ++k) {
                float ss = 0.f;
#pragma unroll
                for (int i = 0; i < 16; ++i) ss += sh2[i][k];
                dst[k] = ss;
            }
        }
    }

    // ---- ticket + final softmax (last of 440 blocks) ----
    __syncthreads();
    if (threadIdx.x == 0) {
        __threadfence();
        sh_last = (atomicAdd(&g_ticket, 1u) == 439u);
    }
    __syncthreads();
    if (sh_last) {
        __threadfence();
        const int t = threadIdx.x;
        if (t < 8) {
            float s6[6] = {0.f, 0.f, 0.f, 0.f, 0.f, 0.f};
            for (int i = 0; i < 50; ++i) {
#pragma unroll
                for (int k = 0; k < 3; ++k)
                    s6[k] += g_part_fine[((size_t)t * 50 + i) * 3 + k];
            }
            for (int i = 0; i < 5; ++i) {
#pragma unroll
                for (int k = 0; k < 3; ++k)
                    s6[3 + k] += g_part_coarse[((size_t)t * 5 + i) * 3 + k];
            }
            const float inv = 1.0f / 6400.0f;
            float a[4][4];
            a[0][0] = a[1][1] = a[2][2] = a[3][3] = 1.0f;
            a[0][1] = a[1][0] = s6[0] * inv;
            a[0][2] = a[2][0] = s6[1] * inv;
            a[0][3] = a[3][0] = s6[2] * inv;
            a[1][2] = a[2][1] = s6[3] * inv;
            a[1][3] = a[3][1] = s6[4] * inv;
            a[2][3] = a[3][2] = s6[5] * inv;
            for (int i = 0; i < 4; ++i) {
                float m = a[i][0];
                for (int j = 1; j < 4; ++j) m = fmaxf(m, a[i][j]);
                float e[4], sum = 0.f;
                for (int j = 0; j < 4; ++j) { e[j] = expf(a[i][j] - m); sum += e[j]; }
                for (int j = 0; j < 4; ++j) out[t * 16 + i * 4 + j] = e[j] / sum;
            }
        }
        if (t == 0) g_ticket = 0;
    }
}

// ---------------------------------------------------------------------------
extern "C" void kernel_launch(void* const* d_in, const int* in_sizes, int n_in,
                              void* d_out, int out_size)
{
    const float* f[4]  = {nullptr, nullptr, nullptr, nullptr};
    const float* w[4]  = {nullptr, nullptr, nullptr, nullptr};
    const float* bs[4] = {nullptr, nullptr, nullptr, nullptr};
    int wi = 0, bi = 0;
    for (int i = 0; i < n_in; ++i) {
        long sz = in_sizes[i];
        const float* p = (const float*)d_in[i];
        if      (sz == 65536)    { if (wi < 4) w[wi++]  = p; }
        else if (sz == 256)      { if (bi < 4) bs[bi++] = p; }
        else if (sz == 13107200) f[0] = p;   // 8*256*6400
        else if (sz == 3276800)  f[1] = p;   // 8*256*1600
        else if (sz == 819200)   f[2] = p;   // 8*256*400
        else if (sz == 204800)   f[3] = p;   // 8*256*100
    }

    prep_w<<<dim3(64, 4), 256>>>(w[0], w[1], w[2], w[3]);

    cudaFuncSetAttribute(gemm_small, cudaFuncAttributeMaxDynamicSharedMemorySize, GEMM_SMEM);
    cudaFuncSetAttribute(gemm0_fused, cudaFuncAttributeMaxDynamicSharedMemorySize, GEMM_SMEM);

    gemm_small<<<144, 512, GEMM_SMEM>>>(f[1], f[2], f[3], bs[1], bs[2], bs[3]);
    gemm0_fused<<<440, 512, GEMM_SMEM>>>(f[0], bs[0], (float*)d_out);
}